// round 2
// baseline (speedup 1.0000x reference)
#include <cuda_runtime.h>
#include <cstddef>

// Problem constants
#define BWIN 2048
#define NTOK 50
#define CDIM 256
#define NH   8
#define HD   32
#define MROWS (BWIN * NTOK)      // 102400

// Scratch (device globals; no allocation allowed)
__device__ float g_qkv[(size_t)MROWS * 768];   // [M, 768]
__device__ float g_att[(size_t)MROWS * CDIM];  // [M, 256] attention output (b,n,h,hd)

// ---------------------------------------------------------------------------
// fp32 SGEMM:  C[M, Nn] = A[M, K=256] * W[Nn, K]^T + bias[Nn]
// BM=BN=128, BK=8, 256 threads, 8x8 per-thread tile split into 4+4 halves.
// ---------------------------------------------------------------------------
__device__ __forceinline__ void gemm256_body(const float* __restrict__ A,
                                             const float* __restrict__ W,
                                             const float* __restrict__ bias,
                                             float* __restrict__ C,
                                             int Nn)
{
    constexpr int K = 256;
    constexpr int NT = K / 8;   // 32 k-tiles

    __shared__ float sA[2][8][128];
    __shared__ float sB[2][8][128];

    const int tid  = threadIdx.x;
    const int m0   = blockIdx.y * 128;
    const int n0   = blockIdx.x * 128;
    const int lrow = tid >> 1;          // 0..127
    const int lcol = (tid & 1) * 4;     // 0 or 4

    const float* Ap = A + (size_t)(m0 + lrow) * K + lcol;
    const float* Wp = W + (size_t)(n0 + lrow) * K + lcol;

    const int tx = tid & 15;            // column group
    const int ty = tid >> 4;            // row group

    float acc[8][8];
#pragma unroll
    for (int i = 0; i < 8; i++)
#pragma unroll
        for (int j = 0; j < 8; j++) acc[i][j] = 0.f;

    // Preload tile 0
    float4 a4 = *(const float4*)Ap;
    float4 b4 = *(const float4*)Wp;
    sA[0][lcol + 0][lrow] = a4.x; sA[0][lcol + 1][lrow] = a4.y;
    sA[0][lcol + 2][lrow] = a4.z; sA[0][lcol + 3][lrow] = a4.w;
    sB[0][lcol + 0][lrow] = b4.x; sB[0][lcol + 1][lrow] = b4.y;
    sB[0][lcol + 2][lrow] = b4.z; sB[0][lcol + 3][lrow] = b4.w;
    __syncthreads();

#pragma unroll
    for (int t = 0; t < NT; ++t) {
        const int cur = t & 1;
        if (t + 1 < NT) {
            a4 = *(const float4*)(Ap + (t + 1) * 8);
            b4 = *(const float4*)(Wp + (t + 1) * 8);
        }
#pragma unroll
        for (int k = 0; k < 8; ++k) {
            float ra[8], rb[8];
            *(float4*)(ra)     = *(const float4*)&sA[cur][k][ty * 4];
            *(float4*)(ra + 4) = *(const float4*)&sA[cur][k][64 + ty * 4];
            *(float4*)(rb)     = *(const float4*)&sB[cur][k][tx * 4];
            *(float4*)(rb + 4) = *(const float4*)&sB[cur][k][64 + tx * 4];
#pragma unroll
            for (int i = 0; i < 8; i++)
#pragma unroll
                for (int j = 0; j < 8; j++)
                    acc[i][j] += ra[i] * rb[j];
        }
        if (t + 1 < NT) {
            const int nxt = cur ^ 1;
            sA[nxt][lcol + 0][lrow] = a4.x; sA[nxt][lcol + 1][lrow] = a4.y;
            sA[nxt][lcol + 2][lrow] = a4.z; sA[nxt][lcol + 3][lrow] = a4.w;
            sB[nxt][lcol + 0][lrow] = b4.x; sB[nxt][lcol + 1][lrow] = b4.y;
            sB[nxt][lcol + 2][lrow] = b4.z; sB[nxt][lcol + 3][lrow] = b4.w;
            __syncthreads();
        }
    }

    // Epilogue (+bias), float4 stores
#pragma unroll
    for (int ih = 0; ih < 2; ih++) {
#pragma unroll
        for (int i = 0; i < 4; i++) {
            const int row = m0 + ih * 64 + ty * 4 + i;
#pragma unroll
            for (int jh = 0; jh < 2; jh++) {
                const int col = n0 + jh * 64 + tx * 4;
                float4 r;
                r.x = acc[ih * 4 + i][jh * 4 + 0] + bias[col + 0];
                r.y = acc[ih * 4 + i][jh * 4 + 1] + bias[col + 1];
                r.z = acc[ih * 4 + i][jh * 4 + 2] + bias[col + 2];
                r.w = acc[ih * 4 + i][jh * 4 + 3] + bias[col + 3];
                *(float4*)&C[(size_t)row * Nn + col] = r;
            }
        }
    }
}

__global__ void __launch_bounds__(256, 2)
qkv_gemm_kernel(const float* __restrict__ x,
                const float* __restrict__ qkv_w,
                const float* __restrict__ qkv_b)
{
    gemm256_body(x, qkv_w, qkv_b, g_qkv, 768);
}

__global__ void __launch_bounds__(256, 2)
proj_gemm_kernel(const float* __restrict__ proj_w,
                 const float* __restrict__ proj_b,
                 float* __restrict__ out)
{
    gemm256_body(g_att, proj_w, proj_b, out, 256);
}

// ---------------------------------------------------------------------------
// Fused attention per (b, h): scores + relpos bias + softmax + AV
// ---------------------------------------------------------------------------
__global__ void __launch_bounds__(256)
attn_kernel(const float* __restrict__ bias_table,
            const int*   __restrict__ rel_idx)
{
    // Row stride 36 floats (16B aligned, conflict-free float4 gather over rows)
    __shared__ float qs[NTOK * 36];
    __shared__ float ks[NTOK * 36];
    __shared__ float vs[NTOK * 36];
    __shared__ float at[NTOK * NTOK];

    const int b   = blockIdx.x >> 3;
    const int h   = blockIdx.x & 7;
    const int tid = threadIdx.x;
    const float scale = 0.17677669529663687f;  // 1/sqrt(32)

    const float* base = g_qkv + (size_t)(b * NTOK) * 768;

    // Load q (pre-scaled), k, v for this head
    for (int idx = tid; idx < NTOK * HD; idx += 256) {
        const int n = idx >> 5;
        const int d = idx & 31;
        const float* row = base + n * 768 + h * HD + d;
        qs[n * 36 + d] = row[0] * scale;
        ks[n * 36 + d] = row[256];
        vs[n * 36 + d] = row[512];
    }
    __syncthreads();

    // Scores + bias
    for (int e = tid; e < NTOK * NTOK; e += 256) {
        const int i = e / NTOK;
        const int j = e - i * NTOK;
        float acc = 0.f;
        if (i > 0 && j > 0)
            acc = bias_table[rel_idx[(i - 1) * 49 + (j - 1)] * NH + h];
        const float4* q4 = (const float4*)(qs + i * 36);
        const float4* k4 = (const float4*)(ks + j * 36);
#pragma unroll
        for (int kk = 0; kk < 8; kk++) {
            const float4 a = q4[kk];
            const float4 c = k4[kk];
            acc += a.x * c.x + a.y * c.y + a.z * c.z + a.w * c.w;
        }
        at[e] = acc;
    }
    __syncthreads();

    // Softmax: warp per row
    const int warp = tid >> 5;
    const int lane = tid & 31;
    for (int i = warp; i < NTOK; i += 8) {
        const float v1 = at[i * NTOK + lane];
        const float v2 = (lane + 32 < NTOK) ? at[i * NTOK + lane + 32] : -1e30f;
        float m = fmaxf(v1, v2);
#pragma unroll
        for (int o = 16; o > 0; o >>= 1)
            m = fmaxf(m, __shfl_xor_sync(0xffffffffu, m, o));
        const float e1 = expf(v1 - m);
        const float e2 = (lane + 32 < NTOK) ? expf(v2 - m) : 0.f;
        float s = e1 + e2;
#pragma unroll
        for (int o = 16; o > 0; o >>= 1)
            s += __shfl_xor_sync(0xffffffffu, s, o);
        const float inv = 1.f / s;
        at[i * NTOK + lane] = e1 * inv;
        if (lane + 32 < NTOK) at[i * NTOK + lane + 32] = e2 * inv;
    }
    __syncthreads();

    // AV: warp per row, lane = head-dim
    for (int i = warp; i < NTOK; i += 8) {
        float acc = 0.f;
#pragma unroll
        for (int j = 0; j < NTOK; j++)
            acc += at[i * NTOK + j] * vs[j * 36 + lane];
        g_att[(size_t)(b * NTOK + i) * CDIM + h * HD + lane] = acc;
    }
}

// ---------------------------------------------------------------------------
extern "C" void kernel_launch(void* const* d_in, const int* in_sizes, int n_in,
                              void* d_out, int out_size)
{
    const float* x          = (const float*)d_in[0];
    const float* qkv_w      = (const float*)d_in[1];
    const float* qkv_b      = (const float*)d_in[2];
    const float* proj_w     = (const float*)d_in[3];
    const float* proj_b     = (const float*)d_in[4];
    const float* bias_table = (const float*)d_in[5];
    const int*   rel_idx    = (const int*)d_in[6];
    float* out = (float*)d_out;

    // QKV: [102400 x 768] = x [102400 x 256] * qkv_w^T
    dim3 g1(768 / 128, MROWS / 128);
    qkv_gemm_kernel<<<g1, 256>>>(x, qkv_w, qkv_b);

    // Attention: one block per (b, h)
    attn_kernel<<<BWIN * NH, 256>>>(bias_table, rel_idx);

    // Proj: [102400 x 256] = att [102400 x 256] * proj_w^T
    dim3 g2(256 / 128, MROWS / 128);
    proj_gemm_kernel<<<g2, 256>>>(proj_w, proj_b, out);
}

// round 4
// speedup vs baseline: 2.0458x; 2.0458x over previous
#include <cuda_runtime.h>
#include <cuda_bf16.h>
#include <cstdint>
#include <cstddef>

// ---------------------------------------------------------------------------
// Problem constants
// ---------------------------------------------------------------------------
#define BWIN 2048
#define NTOK 50
#define CDIM 256
#define NH   8
#define HD   32
#define MROWS (BWIN * NTOK)      // 102400
#define GK   256                 // GEMM K

// ---------------------------------------------------------------------------
// Scratch (device globals; no allocation allowed)
// ---------------------------------------------------------------------------
__device__ float         g_qkv[(size_t)MROWS * 768];    // fp32 qkv output
__device__ __nv_bfloat16 g_xh[(size_t)MROWS * GK];      // x hi
__device__ __nv_bfloat16 g_xl[(size_t)MROWS * GK];      // x lo
__device__ __nv_bfloat16 g_ath[(size_t)MROWS * CDIM];   // attention out hi
__device__ __nv_bfloat16 g_atl[(size_t)MROWS * CDIM];   // attention out lo
__device__ __nv_bfloat16 g_wqh[768 * GK], g_wql[768 * GK];
__device__ __nv_bfloat16 g_wph[CDIM * GK], g_wpl[CDIM * GK];
__device__ float         g_bias[NH * NTOK * NTOK];      // expanded relpos bias

// ---------------------------------------------------------------------------
// Helpers
// ---------------------------------------------------------------------------
__device__ __forceinline__ uint32_t smem_u32(const void* p) {
    uint32_t a;
    asm("{ .reg .u64 t; cvta.to.shared.u64 t, %1; cvt.u32.u64 %0, t; }" : "=r"(a) : "l"(p));
    return a;
}

// fp32 pair -> packed bf16 hi pair + packed bf16 lo pair
__device__ __forceinline__ void split2(float x, float y, uint32_t& hp, uint32_t& lp) {
    asm("cvt.rn.bf16x2.f32 %0, %1, %2;" : "=r"(hp) : "f"(y), "f"(x));
    float hx = __uint_as_float(hp << 16);
    float hy = __uint_as_float(hp & 0xFFFF0000u);
    float rx = x - hx, ry = y - hy;
    asm("cvt.rn.bf16x2.f32 %0, %1, %2;" : "=r"(lp) : "f"(ry), "f"(rx));
}

#define LDSM_X4(r, a) asm volatile( \
    "ldmatrix.sync.aligned.m8n8.x4.shared.b16 {%0,%1,%2,%3}, [%4];" \
    : "=r"((r)[0]), "=r"((r)[1]), "=r"((r)[2]), "=r"((r)[3]) : "r"(a))
#define LDSM_X2(r, a) asm volatile( \
    "ldmatrix.sync.aligned.m8n8.x2.shared.b16 {%0,%1}, [%2];" \
    : "=r"((r)[0]), "=r"((r)[1]) : "r"(a))

__device__ __forceinline__ void mma16816(float* d, const uint32_t* a, const uint32_t* b) {
    asm volatile(
        "mma.sync.aligned.m16n8k16.row.col.f32.bf16.bf16.f32 "
        "{%0,%1,%2,%3},{%4,%5,%6,%7},{%8,%9},{%0,%1,%2,%3};"
        : "+f"(d[0]), "+f"(d[1]), "+f"(d[2]), "+f"(d[3])
        : "r"(a[0]), "r"(a[1]), "r"(a[2]), "r"(a[3]), "r"(b[0]), "r"(b[1]));
}

#define CP_ASYNC16(dst, src) asm volatile( \
    "cp.async.cg.shared.global [%0], [%1], 16;" :: "r"(dst), "l"(src))
#define CP_COMMIT() asm volatile("cp.async.commit_group;" ::: "memory")
#define CP_WAIT(n)  asm volatile("cp.async.wait_group %0;" :: "n"(n) : "memory")

// ---------------------------------------------------------------------------
// fp32 -> hi/lo bf16 split converter
// ---------------------------------------------------------------------------
__global__ void conv_split(const float* __restrict__ src,
                           __nv_bfloat16* __restrict__ dh,
                           __nv_bfloat16* __restrict__ dl, int n4)
{
    int i = blockIdx.x * 256 + threadIdx.x;
    if (i >= n4) return;
    float4 v = ((const float4*)src)[i];
    uint32_t h01, l01, h23, l23;
    split2(v.x, v.y, h01, l01);
    split2(v.z, v.w, h23, l23);
    ((uint2*)dh)[i] = make_uint2(h01, h23);
    ((uint2*)dl)[i] = make_uint2(l01, l23);
}

// ---------------------------------------------------------------------------
// Split-bf16 tensor-core GEMM: C[M, Nn] = A[M,256] * W[Nn,256]^T + bias
// CTA 128x128, BK=32 (8 stages), double-buffered cp.async, mma.sync m16n8k16.
// smem stage: Ah(8K) Al(8K) Bh(8K) Bl(8K) = 32KB; 2 stages = 64KB dynamic.
// ---------------------------------------------------------------------------
#define GEMM_SMEM 65536

__global__ void __launch_bounds__(256, 1)
gemm_mma(const __nv_bfloat16* __restrict__ Ah, const __nv_bfloat16* __restrict__ Al,
         const __nv_bfloat16* __restrict__ Wh, const __nv_bfloat16* __restrict__ Wl,
         const float* __restrict__ bias, float* __restrict__ C, int Nn)
{
    extern __shared__ char smem[];
    const uint32_t sbase = smem_u32(smem);

    const int tid  = threadIdx.x;
    const int lane = tid & 31;
    const int warp = tid >> 5;
    const int m0 = blockIdx.y * 128;
    const int n0 = blockIdx.x * 128;
    const int wm = warp & 1;    // 2 M-groups of 64
    const int wn = warp >> 1;   // 4 N-groups of 32

    float acc[4][4][4];
#pragma unroll
    for (int i = 0; i < 4; i++)
#pragma unroll
        for (int j = 0; j < 4; j++)
#pragma unroll
            for (int r = 0; r < 4; r++) acc[i][j][r] = 0.f;

    // --- async stage fill: 2048 16B-chunks, 8 per thread, arr uniform per it
    auto issue = [&](int s) {
        const uint32_t stb = sbase + (uint32_t)(s & 1) * 32768u;
#pragma unroll
        for (int it = 0; it < 8; ++it) {
            int f   = it * 256 + tid;
            int arr = f >> 9;           // 0:Ah 1:Al 2:Bh 3:Bl (uniform per it)
            int g   = f & 511;
            int row = g >> 2, c = g & 3;
            uint32_t dst = stb + arr * 8192 + row * 64 + 16 * (c ^ ((row >> 1) & 3));
            const __nv_bfloat16* src;
            if      (arr == 0) src = Ah + (size_t)(m0 + row) * GK + s * 32 + c * 8;
            else if (arr == 1) src = Al + (size_t)(m0 + row) * GK + s * 32 + c * 8;
            else if (arr == 2) src = Wh + (size_t)(n0 + row) * GK + s * 32 + c * 8;
            else               src = Wl + (size_t)(n0 + row) * GK + s * 32 + c * 8;
            CP_ASYNC16(dst, src);
        }
        CP_COMMIT();
    };

    issue(0);

#pragma unroll
    for (int s = 0; s < 8; ++s) {
        if (s + 1 < 8) { issue(s + 1); CP_WAIT(1); }
        else           { CP_WAIT(0); }
        __syncthreads();

        const uint32_t stb = sbase + (uint32_t)(s & 1) * 32768u;
#pragma unroll
        for (int ks = 0; ks < 2; ++ks) {
            uint32_t ah[4][4], al[4][4], bh[4][2], bl[4][2];
#pragma unroll
            for (int i = 0; i < 4; ++i) {
                int r = wm * 64 + i * 16 + (lane & 15);
                int c = ks * 2 + (lane >> 4);
                uint32_t ad = stb + r * 64 + 16 * (c ^ ((r >> 1) & 3));
                LDSM_X4(ah[i], ad);
                LDSM_X4(al[i], ad + 8192);
            }
#pragma unroll
            for (int j = 0; j < 4; ++j) {
                int r = wn * 32 + j * 8 + (lane & 7);
                int c = ks * 2 + ((lane >> 3) & 1);
                uint32_t bd = stb + 16384 + r * 64 + 16 * (c ^ ((r >> 1) & 3));
                LDSM_X2(bh[j], bd);
                LDSM_X2(bl[j], bd + 8192);
            }
#pragma unroll
            for (int i = 0; i < 4; ++i)
#pragma unroll
                for (int j = 0; j < 4; ++j) {
                    mma16816(acc[i][j], ah[i], bh[j]);
                    mma16816(acc[i][j], ah[i], bl[j]);
                    mma16816(acc[i][j], al[i], bh[j]);
                }
        }
        __syncthreads();
    }

    // --- epilogue: +bias, float2 stores
#pragma unroll
    for (int i = 0; i < 4; ++i) {
        int mb = m0 + wm * 64 + i * 16 + (lane >> 2);
#pragma unroll
        for (int j = 0; j < 4; ++j) {
            int nb = n0 + wn * 32 + j * 8 + (lane & 3) * 2;
            float bx = bias[nb], by = bias[nb + 1];
            float2 v0 = make_float2(acc[i][j][0] + bx, acc[i][j][1] + by);
            float2 v1 = make_float2(acc[i][j][2] + bx, acc[i][j][3] + by);
            *(float2*)&C[(size_t)mb * Nn + nb]       = v0;
            *(float2*)&C[(size_t)(mb + 8) * Nn + nb] = v1;
        }
    }
}

// ---------------------------------------------------------------------------
// Bias expansion: g_bias[h][i][j]
// ---------------------------------------------------------------------------
__global__ void bias_expand(const float* __restrict__ bt, const int* __restrict__ ri)
{
    int idx = blockIdx.x * 256 + threadIdx.x;
    if (idx >= NH * NTOK * NTOK) return;
    int h = idx / (NTOK * NTOK);
    int rem = idx - h * NTOK * NTOK;
    int i = rem / NTOK, j = rem - i * NTOK;
    float v = 0.f;
    if (i > 0 && j > 0) v = bt[ri[(i - 1) * 49 + (j - 1)] * NH + h];
    g_bias[idx] = v;
}

// ---------------------------------------------------------------------------
// Attention per (b, h): k & v in registers, register softmax.
// Emits hi/lo bf16 split directly (proj GEMM input).
// ---------------------------------------------------------------------------
__global__ void __launch_bounds__(128)
attn2()
{
    __shared__ float qs[NTOK * 36];
    __shared__ float kt[32 * 65];
    __shared__ float vs[NTOK * 36];
    __shared__ float at[NTOK * 52];

    const int b = blockIdx.x >> 3, h = blockIdx.x & 7;
    const int tid = threadIdx.x, warp = tid >> 5, lane = tid & 31;
    const float scale = 0.17677669529663687f;

    for (int i = tid; i < 32 * 65; i += 128) kt[i] = 0.f;
    __syncthreads();

    const float* base = g_qkv + (size_t)b * NTOK * 768 + h * HD;
    for (int idx = tid; idx < NTOK * HD; idx += 128) {
        int n = idx >> 5, d = idx & 31;
        const float* r = base + n * 768 + d;
        qs[n * 36 + d] = r[0] * scale;
        kt[d * 65 + n] = r[256];
        vs[n * 36 + d] = r[512];
    }
    __syncthreads();

    float k0[32], k1[32];
#pragma unroll
    for (int d = 0; d < 32; ++d) { k0[d] = kt[d * 65 + lane]; k1[d] = kt[d * 65 + lane + 32]; }

    const float* gbh = g_bias + h * (NTOK * NTOK);
    const bool j2ok = (lane + 32) < NTOK;

    for (int i = warp; i < NTOK; i += 4) {
        float a0 = gbh[i * NTOK + lane];
        float a1 = j2ok ? gbh[i * NTOK + lane + 32] : -1e30f;
#pragma unroll
        for (int d = 0; d < 32; d += 4) {
            float4 q4 = *(const float4*)&qs[i * 36 + d];
            a0 += q4.x * k0[d] + q4.y * k0[d + 1] + q4.z * k0[d + 2] + q4.w * k0[d + 3];
            a1 += q4.x * k1[d] + q4.y * k1[d + 1] + q4.z * k1[d + 2] + q4.w * k1[d + 3];
        }
        float m = fmaxf(a0, a1);
#pragma unroll
        for (int o = 16; o > 0; o >>= 1) m = fmaxf(m, __shfl_xor_sync(0xffffffffu, m, o));
        float e0 = __expf(a0 - m);
        float e1 = j2ok ? __expf(a1 - m) : 0.f;
        float s = e0 + e1;
#pragma unroll
        for (int o = 16; o > 0; o >>= 1) s += __shfl_xor_sync(0xffffffffu, s, o);
        float inv = 1.f / s;
        at[i * 52 + lane] = e0 * inv;
        if (lane + 32 < 52) at[i * 52 + lane + 32] = j2ok ? e1 * inv : 0.f;
    }
    __syncwarp();

    float vr[52];
#pragma unroll
    for (int j = 0; j < NTOK; ++j) vr[j] = vs[j * 36 + lane];
    vr[50] = 0.f; vr[51] = 0.f;

    for (int i = warp; i < NTOK; i += 4) {
        float acc = 0.f;
#pragma unroll
        for (int j4 = 0; j4 < 13; ++j4) {
            float4 p = *(const float4*)&at[i * 52 + j4 * 4];
            acc += p.x * vr[j4 * 4] + p.y * vr[j4 * 4 + 1] + p.z * vr[j4 * 4 + 2] + p.w * vr[j4 * 4 + 3];
        }
        size_t idx = (size_t)(b * NTOK + i) * CDIM + h * HD + lane;
        __nv_bfloat16 hv = __float2bfloat16(acc);
        g_ath[idx] = hv;
        g_atl[idx] = __float2bfloat16(acc - __bfloat162float(hv));
    }
}

// ---------------------------------------------------------------------------
extern "C" void kernel_launch(void* const* d_in, const int* in_sizes, int n_in,
                              void* d_out, int out_size)
{
    const float* x          = (const float*)d_in[0];
    const float* qkv_w      = (const float*)d_in[1];
    const float* qkv_b      = (const float*)d_in[2];
    const float* proj_w     = (const float*)d_in[3];
    const float* proj_b     = (const float*)d_in[4];
    const float* bias_table = (const float*)d_in[5];
    const int*   rel_idx    = (const int*)d_in[6];
    float* out = (float*)d_out;

    static bool attr_set = false;
    if (!attr_set) {
        cudaFuncSetAttribute(gemm_mma, cudaFuncAttributeMaxDynamicSharedMemorySize, GEMM_SMEM);
        attr_set = true;
    }

    __nv_bfloat16 *xh, *xl, *wqh, *wql, *wph, *wpl, *ath, *atl;
    float *qkvp;
    cudaGetSymbolAddress((void**)&xh,  g_xh);
    cudaGetSymbolAddress((void**)&xl,  g_xl);
    cudaGetSymbolAddress((void**)&wqh, g_wqh);
    cudaGetSymbolAddress((void**)&wql, g_wql);
    cudaGetSymbolAddress((void**)&wph, g_wph);
    cudaGetSymbolAddress((void**)&wpl, g_wpl);
    cudaGetSymbolAddress((void**)&ath, g_ath);
    cudaGetSymbolAddress((void**)&atl, g_atl);
    cudaGetSymbolAddress((void**)&qkvp, g_qkv);

    // Split conversions
    conv_split<<<(MROWS * GK / 4 + 255) / 256, 256>>>(x, xh, xl, MROWS * GK / 4);
    conv_split<<<(768 * GK / 4 + 255) / 256, 256>>>(qkv_w, wqh, wql, 768 * GK / 4);
    conv_split<<<(CDIM * GK / 4 + 255) / 256, 256>>>(proj_w, wph, wpl, CDIM * GK / 4);
    bias_expand<<<(NH * NTOK * NTOK + 255) / 256, 256>>>(bias_table, rel_idx);

    // QKV: [102400 x 768]
    gemm_mma<<<dim3(768 / 128, MROWS / 128), 256, GEMM_SMEM>>>(xh, xl, wqh, wql, qkv_b, qkvp, 768);

    // Attention
    attn2<<<BWIN * NH, 128>>>();

    // Proj: [102400 x 256]
    gemm_mma<<<dim3(256 / 128, MROWS / 128), 256, GEMM_SMEM>>>(ath, atl, wph, wpl, proj_b, out, 256);
}

// round 5
// speedup vs baseline: 2.8536x; 1.3949x over previous
#include <cuda_runtime.h>
#include <cuda_bf16.h>
#include <cstdint>
#include <cstddef>

// ---------------------------------------------------------------------------
// Problem constants
// ---------------------------------------------------------------------------
#define BWIN 2048
#define NTOK 50
#define CDIM 256
#define NH   8
#define HD   32
#define MROWS (BWIN * NTOK)      // 102400
#define GK   256                 // GEMM K

// ---------------------------------------------------------------------------
// Scratch (device globals; no allocation allowed)
// ---------------------------------------------------------------------------
__device__ float         g_qkv[(size_t)MROWS * 768];    // fp32 qkv output
__device__ __nv_bfloat16 g_xh[(size_t)MROWS * GK];      // x hi
__device__ __nv_bfloat16 g_xl[(size_t)MROWS * GK];      // x lo
__device__ __nv_bfloat16 g_ath[(size_t)MROWS * CDIM];   // attention out hi
__device__ __nv_bfloat16 g_atl[(size_t)MROWS * CDIM];   // attention out lo
__device__ __nv_bfloat16 g_wqh[768 * GK], g_wql[768 * GK];
__device__ __nv_bfloat16 g_wph[CDIM * GK], g_wpl[CDIM * GK];
__device__ float         g_bias[NH * NTOK * NTOK + 64]; // expanded bias (+pad)

// ---------------------------------------------------------------------------
// Helpers
// ---------------------------------------------------------------------------
__device__ __forceinline__ uint32_t smem_u32(const void* p) {
    uint32_t a;
    asm("{ .reg .u64 t; cvta.to.shared.u64 t, %1; cvt.u32.u64 %0, t; }" : "=r"(a) : "l"(p));
    return a;
}

// fp32 pair -> packed bf16 hi pair + packed bf16 lo pair
__device__ __forceinline__ void split2(float x, float y, uint32_t& hp, uint32_t& lp) {
    asm("cvt.rn.bf16x2.f32 %0, %1, %2;" : "=r"(hp) : "f"(y), "f"(x));
    float hx = __uint_as_float(hp << 16);
    float hy = __uint_as_float(hp & 0xFFFF0000u);
    float rx = x - hx, ry = y - hy;
    asm("cvt.rn.bf16x2.f32 %0, %1, %2;" : "=r"(lp) : "f"(ry), "f"(rx));
}

#define LDSM_X4(r, a) asm volatile( \
    "ldmatrix.sync.aligned.m8n8.x4.shared.b16 {%0,%1,%2,%3}, [%4];" \
    : "=r"((r)[0]), "=r"((r)[1]), "=r"((r)[2]), "=r"((r)[3]) : "r"(a))
#define LDSM_X2(r, a) asm volatile( \
    "ldmatrix.sync.aligned.m8n8.x2.shared.b16 {%0,%1}, [%2];" \
    : "=r"((r)[0]), "=r"((r)[1]) : "r"(a))
#define LDSM_X4_T(r, a) asm volatile( \
    "ldmatrix.sync.aligned.m8n8.x4.trans.shared.b16 {%0,%1,%2,%3}, [%4];" \
    : "=r"((r)[0]), "=r"((r)[1]), "=r"((r)[2]), "=r"((r)[3]) : "r"(a))

__device__ __forceinline__ void mma16816(float* d, const uint32_t* a, const uint32_t* b) {
    asm volatile(
        "mma.sync.aligned.m16n8k16.row.col.f32.bf16.bf16.f32 "
        "{%0,%1,%2,%3},{%4,%5,%6,%7},{%8,%9},{%0,%1,%2,%3};"
        : "+f"(d[0]), "+f"(d[1]), "+f"(d[2]), "+f"(d[3])
        : "r"(a[0]), "r"(a[1]), "r"(a[2]), "r"(a[3]), "r"(b[0]), "r"(b[1]));
}

#define CP_ASYNC16(dst, src) asm volatile( \
    "cp.async.cg.shared.global [%0], [%1], 16;" :: "r"(dst), "l"(src))
#define CP_COMMIT() asm volatile("cp.async.commit_group;" ::: "memory")
#define CP_WAIT(n)  asm volatile("cp.async.wait_group %0;" :: "n"(n) : "memory")
#define STS64(a, x, y) asm volatile("st.shared.v2.b32 [%0], {%1,%2};" :: "r"(a), "r"(x), "r"(y) : "memory")

// Swizzled shared address for 64B rows: conflict-free ldmatrix + stores
__device__ __forceinline__ uint32_t swz(uint32_t base, int r, int ch) {
    return base + r * 64 + 16 * (ch ^ ((r >> 1) & 3));
}

// ---------------------------------------------------------------------------
// fp32 -> hi/lo bf16 split converter
// ---------------------------------------------------------------------------
__global__ void conv_split(const float* __restrict__ src,
                           __nv_bfloat16* __restrict__ dh,
                           __nv_bfloat16* __restrict__ dl, int n4)
{
    int i = blockIdx.x * 256 + threadIdx.x;
    if (i >= n4) return;
    float4 v = ((const float4*)src)[i];
    uint32_t h01, l01, h23, l23;
    split2(v.x, v.y, h01, l01);
    split2(v.z, v.w, h23, l23);
    ((uint2*)dh)[i] = make_uint2(h01, h23);
    ((uint2*)dl)[i] = make_uint2(l01, l23);
}

// ---------------------------------------------------------------------------
// Split-bf16 tensor-core GEMM (unchanged from R4-pass version)
// ---------------------------------------------------------------------------
#define GEMM_SMEM 65536

__global__ void __launch_bounds__(256, 1)
gemm_mma(const __nv_bfloat16* __restrict__ Ah, const __nv_bfloat16* __restrict__ Al,
         const __nv_bfloat16* __restrict__ Wh, const __nv_bfloat16* __restrict__ Wl,
         const float* __restrict__ bias, float* __restrict__ C, int Nn)
{
    extern __shared__ char smem[];
    const uint32_t sbase = smem_u32(smem);

    const int tid  = threadIdx.x;
    const int lane = tid & 31;
    const int warp = tid >> 5;
    const int m0 = blockIdx.y * 128;
    const int n0 = blockIdx.x * 128;
    const int wm = warp & 1;
    const int wn = warp >> 1;

    float acc[4][4][4];
#pragma unroll
    for (int i = 0; i < 4; i++)
#pragma unroll
        for (int j = 0; j < 4; j++)
#pragma unroll
            for (int r = 0; r < 4; r++) acc[i][j][r] = 0.f;

    auto issue = [&](int s) {
        const uint32_t stb = sbase + (uint32_t)(s & 1) * 32768u;
#pragma unroll
        for (int it = 0; it < 8; ++it) {
            int f   = it * 256 + tid;
            int arr = f >> 9;
            int g   = f & 511;
            int row = g >> 2, c = g & 3;
            uint32_t dst = stb + arr * 8192 + row * 64 + 16 * (c ^ ((row >> 1) & 3));
            const __nv_bfloat16* src;
            if      (arr == 0) src = Ah + (size_t)(m0 + row) * GK + s * 32 + c * 8;
            else if (arr == 1) src = Al + (size_t)(m0 + row) * GK + s * 32 + c * 8;
            else if (arr == 2) src = Wh + (size_t)(n0 + row) * GK + s * 32 + c * 8;
            else               src = Wl + (size_t)(n0 + row) * GK + s * 32 + c * 8;
            CP_ASYNC16(dst, src);
        }
        CP_COMMIT();
    };

    issue(0);

#pragma unroll
    for (int s = 0; s < 8; ++s) {
        if (s + 1 < 8) { issue(s + 1); CP_WAIT(1); }
        else           { CP_WAIT(0); }
        __syncthreads();

        const uint32_t stb = sbase + (uint32_t)(s & 1) * 32768u;
#pragma unroll
        for (int ks = 0; ks < 2; ++ks) {
            uint32_t ah[4][4], al[4][4], bh[4][2], bl[4][2];
#pragma unroll
            for (int i = 0; i < 4; ++i) {
                int r = wm * 64 + i * 16 + (lane & 15);
                int c = ks * 2 + (lane >> 4);
                uint32_t ad = stb + r * 64 + 16 * (c ^ ((r >> 1) & 3));
                LDSM_X4(ah[i], ad);
                LDSM_X4(al[i], ad + 8192);
            }
#pragma unroll
            for (int j = 0; j < 4; ++j) {
                int r = wn * 32 + j * 8 + (lane & 7);
                int c = ks * 2 + ((lane >> 3) & 1);
                uint32_t bd = stb + 16384 + r * 64 + 16 * (c ^ ((r >> 1) & 3));
                LDSM_X2(bh[j], bd);
                LDSM_X2(bl[j], bd + 8192);
            }
#pragma unroll
            for (int i = 0; i < 4; ++i)
#pragma unroll
                for (int j = 0; j < 4; ++j) {
                    mma16816(acc[i][j], ah[i], bh[j]);
                    mma16816(acc[i][j], ah[i], bl[j]);
                    mma16816(acc[i][j], al[i], bh[j]);
                }
        }
        __syncthreads();
    }

#pragma unroll
    for (int i = 0; i < 4; ++i) {
        int mb = m0 + wm * 64 + i * 16 + (lane >> 2);
#pragma unroll
        for (int j = 0; j < 4; ++j) {
            int nb = n0 + wn * 32 + j * 8 + (lane & 3) * 2;
            float bx = bias[nb], by = bias[nb + 1];
            float2 v0 = make_float2(acc[i][j][0] + bx, acc[i][j][1] + by);
            float2 v1 = make_float2(acc[i][j][2] + bx, acc[i][j][3] + by);
            *(float2*)&C[(size_t)mb * Nn + nb]       = v0;
            *(float2*)&C[(size_t)(mb + 8) * Nn + nb] = v1;
        }
    }
}

// ---------------------------------------------------------------------------
// Bias expansion
// ---------------------------------------------------------------------------
__global__ void bias_expand(const float* __restrict__ bt, const int* __restrict__ ri)
{
    int idx = blockIdx.x * 256 + threadIdx.x;
    if (idx >= NH * NTOK * NTOK) return;
    int h = idx / (NTOK * NTOK);
    int rem = idx - h * NTOK * NTOK;
    int i = rem / NTOK, j = rem - i * NTOK;
    float v = 0.f;
    if (i > 0 && j > 0) v = bt[ri[(i - 1) * 49 + (j - 1)] * NH + h];
    g_bias[idx] = v;
}

// ---------------------------------------------------------------------------
// Tensor-core attention: one warp per head, 4 heads per CTA.
// S = QK^T (split bf16, 3 MMAs), fragment softmax, O = P V (split, 3 MMAs).
// smem per warp: Qh Ql Kh Kl Vh Vl, each 64 rows x 32 cols bf16 (4KB) = 24KB.
// ---------------------------------------------------------------------------
#define ATTN_SMEM (4 * 24576)

__global__ void __launch_bounds__(128)
attn_tc()
{
    extern __shared__ char asm_smem[];
    const uint32_t sbase = smem_u32(asm_smem);

    const int tid = threadIdx.x, warp = tid >> 5, lane = tid & 31;
    const int b = blockIdx.x >> 1;
    const int h = (blockIdx.x & 1) * 4 + warp;
    const float scale = 0.17677669529663687f;

    const uint32_t wb = sbase + warp * 24576u;
    const uint32_t Qh = wb, Ql = wb + 4096, Kh = wb + 8192, Kl = wb + 12288,
                   Vh = wb + 16384, Vl = wb + 20480;

    // Zero V pad rows 50..63 (both splits)
    for (int i = lane; i < 112; i += 32) {
        int row = 50 + (i >> 3);
        uint32_t a = row * 64 + (i & 7) * 8;
        STS64(Vh + a, 0u, 0u);
        STS64(Vl + a, 0u, 0u);
    }

    // Load q (scaled), k, v -> hi/lo bf16 swizzled smem
    const float* src = g_qkv + (size_t)b * NTOK * 768 + h * HD;
#pragma unroll
    for (int it = 0; it < 13; ++it) {
        int f = it * 32 + lane;
        if (f < 400) {
            int row = f >> 3, c4 = (f & 7) << 2;
            const float* p = src + row * 768 + c4;
            float4 q = *(const float4*)p;
            float4 kk = *(const float4*)(p + 256);
            float4 vv = *(const float4*)(p + 512);
            q.x *= scale; q.y *= scale; q.z *= scale; q.w *= scale;
            uint32_t ad = swz(0, row, c4 >> 3) + ((c4 & 4) << 1);
            uint32_t a01, b01, a23, b23;
            split2(q.x, q.y, a01, b01); split2(q.z, q.w, a23, b23);
            STS64(Qh + ad, a01, a23); STS64(Ql + ad, b01, b23);
            split2(kk.x, kk.y, a01, b01); split2(kk.z, kk.w, a23, b23);
            STS64(Kh + ad, a01, a23); STS64(Kl + ad, b01, b23);
            split2(vv.x, vv.y, a01, b01); split2(vv.z, vv.w, a23, b23);
            STS64(Vh + ad, a01, a23); STS64(Vl + ad, b01, b23);
        }
    }
    __syncwarp();

    const float* gbh = g_bias + h * (NTOK * NTOK);
    const int qrow = lane >> 2;          // 0..7
    const int j0l  = (lane & 3) * 2;

    // Two halves of M (rows 0-31, 32-63) to bound register pressure
#pragma unroll
    for (int half = 0; half < 2; ++half) {
        float S[2][7][4];
#pragma unroll
        for (int m = 0; m < 2; m++)
#pragma unroll
            for (int nt = 0; nt < 7; nt++)
#pragma unroll
                for (int r = 0; r < 4; r++) S[m][nt][r] = 0.f;

        // ---- S = Q K^T, 3-way split ----
#pragma unroll
        for (int ks = 0; ks < 2; ++ks) {
            uint32_t qh[2][4], ql[2][4];
#pragma unroll
            for (int m = 0; m < 2; ++m) {
                int mt = half * 2 + m;
                int r = mt * 16 + (lane & 15);
                int ch = ks * 2 + (lane >> 4);
                LDSM_X4(qh[m], swz(Qh, r, ch));
                LDSM_X4(ql[m], swz(Ql, r, ch));
            }
#pragma unroll
            for (int nt = 0; nt < 7; ++nt) {
                uint32_t kh[2], kl[2];
                int r = nt * 8 + (lane & 7);
                int ch = ks * 2 + ((lane >> 3) & 1);
                LDSM_X2(kh, swz(Kh, r, ch));
                LDSM_X2(kl, swz(Kl, r, ch));
#pragma unroll
                for (int m = 0; m < 2; ++m) {
                    mma16816(S[m][nt], qh[m], kh);
                    mma16816(S[m][nt], qh[m], kl);
                    mma16816(S[m][nt], ql[m], kh);
                }
            }
        }

        // ---- bias + mask ----
#pragma unroll
        for (int m = 0; m < 2; ++m) {
            int mt = half * 2 + m;
            int r0 = mt * 16 + qrow, r1 = r0 + 8;
#pragma unroll
            for (int nt = 0; nt < 7; ++nt) {
                int j0 = nt * 8 + j0l;
                if (j0 < NTOK) {
                    if (r0 < NTOK) {
                        float2 bv = *(const float2*)&gbh[r0 * NTOK + j0];
                        S[m][nt][0] += bv.x; S[m][nt][1] += bv.y;
                    }
                    if (r1 < NTOK) {
                        float2 bv = *(const float2*)&gbh[r1 * NTOK + j0];
                        S[m][nt][2] += bv.x; S[m][nt][3] += bv.y;
                    }
                } else {
                    S[m][nt][0] = -1e30f; S[m][nt][2] = -1e30f;
                }
                if (j0 + 1 >= NTOK) { S[m][nt][1] = -1e30f; S[m][nt][3] = -1e30f; }
            }
        }

        // ---- softmax (quad reductions) ----
#pragma unroll
        for (int m = 0; m < 2; ++m) {
            float mx0 = -1e30f, mx1 = -1e30f;
#pragma unroll
            for (int nt = 0; nt < 7; ++nt) {
                mx0 = fmaxf(mx0, fmaxf(S[m][nt][0], S[m][nt][1]));
                mx1 = fmaxf(mx1, fmaxf(S[m][nt][2], S[m][nt][3]));
            }
            mx0 = fmaxf(mx0, __shfl_xor_sync(0xffffffffu, mx0, 1));
            mx0 = fmaxf(mx0, __shfl_xor_sync(0xffffffffu, mx0, 2));
            mx1 = fmaxf(mx1, __shfl_xor_sync(0xffffffffu, mx1, 1));
            mx1 = fmaxf(mx1, __shfl_xor_sync(0xffffffffu, mx1, 2));
            float s0 = 0.f, s1 = 0.f;
#pragma unroll
            for (int nt = 0; nt < 7; ++nt) {
                S[m][nt][0] = __expf(S[m][nt][0] - mx0); s0 += S[m][nt][0];
                S[m][nt][1] = __expf(S[m][nt][1] - mx0); s0 += S[m][nt][1];
                S[m][nt][2] = __expf(S[m][nt][2] - mx1); s1 += S[m][nt][2];
                S[m][nt][3] = __expf(S[m][nt][3] - mx1); s1 += S[m][nt][3];
            }
            s0 += __shfl_xor_sync(0xffffffffu, s0, 1);
            s0 += __shfl_xor_sync(0xffffffffu, s0, 2);
            s1 += __shfl_xor_sync(0xffffffffu, s1, 1);
            s1 += __shfl_xor_sync(0xffffffffu, s1, 2);
            float i0 = 1.f / s0, i1 = 1.f / s1;
#pragma unroll
            for (int nt = 0; nt < 7; ++nt) {
                S[m][nt][0] *= i0; S[m][nt][1] *= i0;
                S[m][nt][2] *= i1; S[m][nt][3] *= i1;
            }
        }

        // ---- O = P V, 3-way split; P packed from S fragments ----
        float O[2][4][4];
#pragma unroll
        for (int m = 0; m < 2; m++)
#pragma unroll
            for (int nt = 0; nt < 4; nt++)
#pragma unroll
                for (int r = 0; r < 4; r++) O[m][nt][r] = 0.f;

#pragma unroll
        for (int kt = 0; kt < 4; ++kt) {
            uint32_t vh[2][4], vl[2][4];
#pragma unroll
            for (int np = 0; np < 2; ++np) {
                int r = kt * 16 + (lane & 15);
                int ch = np * 2 + (lane >> 4);
                LDSM_X4_T(vh[np], swz(Vh, r, ch));
                LDSM_X4_T(vl[np], swz(Vl, r, ch));
            }
#pragma unroll
            for (int m = 0; m < 2; ++m) {
                uint32_t ah[4], al[4];
                int ntA = 2 * kt, ntB = 2 * kt + 1;
                split2(S[m][ntA][0], S[m][ntA][1], ah[0], al[0]);
                split2(S[m][ntA][2], S[m][ntA][3], ah[1], al[1]);
                if (ntB < 7) {
                    split2(S[m][ntB][0], S[m][ntB][1], ah[2], al[2]);
                    split2(S[m][ntB][2], S[m][ntB][3], ah[3], al[3]);
                } else {
                    ah[2] = ah[3] = al[2] = al[3] = 0u;
                }
#pragma unroll
                for (int nt = 0; nt < 4; ++nt) {
                    const uint32_t* bhf = &vh[nt >> 1][(nt & 1) * 2];
                    const uint32_t* blf = &vl[nt >> 1][(nt & 1) * 2];
                    mma16816(O[m][nt], ah, bhf);
                    mma16816(O[m][nt], ah, blf);
                    mma16816(O[m][nt], al, bhf);
                }
            }
        }

        // ---- store O rows < 50 as hi/lo bf16 ----
#pragma unroll
        for (int m = 0; m < 2; ++m) {
            int mt = half * 2 + m;
            int r0 = mt * 16 + qrow, r1 = r0 + 8;
#pragma unroll
            for (int nt = 0; nt < 4; ++nt) {
                int d0 = h * HD + nt * 8 + j0l;
                uint32_t hp, lp;
                if (r0 < NTOK) {
                    size_t idx = (size_t)(b * NTOK + r0) * CDIM + d0;
                    split2(O[m][nt][0], O[m][nt][1], hp, lp);
                    *(uint32_t*)&g_ath[idx] = hp;
                    *(uint32_t*)&g_atl[idx] = lp;
                }
                if (r1 < NTOK) {
                    size_t idx = (size_t)(b * NTOK + r1) * CDIM + d0;
                    split2(O[m][nt][2], O[m][nt][3], hp, lp);
                    *(uint32_t*)&g_ath[idx] = hp;
                    *(uint32_t*)&g_atl[idx] = lp;
                }
            }
        }
    }
}

// ---------------------------------------------------------------------------
extern "C" void kernel_launch(void* const* d_in, const int* in_sizes, int n_in,
                              void* d_out, int out_size)
{
    const float* x          = (const float*)d_in[0];
    const float* qkv_w      = (const float*)d_in[1];
    const float* qkv_b      = (const float*)d_in[2];
    const float* proj_w     = (const float*)d_in[3];
    const float* proj_b     = (const float*)d_in[4];
    const float* bias_table = (const float*)d_in[5];
    const int*   rel_idx    = (const int*)d_in[6];
    float* out = (float*)d_out;

    static bool attr_set = false;
    if (!attr_set) {
        cudaFuncSetAttribute(gemm_mma, cudaFuncAttributeMaxDynamicSharedMemorySize, GEMM_SMEM);
        cudaFuncSetAttribute(attn_tc,  cudaFuncAttributeMaxDynamicSharedMemorySize, ATTN_SMEM);
        attr_set = true;
    }

    __nv_bfloat16 *xh, *xl, *wqh, *wql, *wph, *wpl, *ath, *atl;
    float *qkvp;
    cudaGetSymbolAddress((void**)&xh,  g_xh);
    cudaGetSymbolAddress((void**)&xl,  g_xl);
    cudaGetSymbolAddress((void**)&wqh, g_wqh);
    cudaGetSymbolAddress((void**)&wql, g_wql);
    cudaGetSymbolAddress((void**)&wph, g_wph);
    cudaGetSymbolAddress((void**)&wpl, g_wpl);
    cudaGetSymbolAddress((void**)&ath, g_ath);
    cudaGetSymbolAddress((void**)&atl, g_atl);
    cudaGetSymbolAddress((void**)&qkvp, g_qkv);

    conv_split<<<(MROWS * GK / 4 + 255) / 256, 256>>>(x, xh, xl, MROWS * GK / 4);
    conv_split<<<(768 * GK / 4 + 255) / 256, 256>>>(qkv_w, wqh, wql, 768 * GK / 4);
    conv_split<<<(CDIM * GK / 4 + 255) / 256, 256>>>(proj_w, wph, wpl, CDIM * GK / 4);
    bias_expand<<<(NH * NTOK * NTOK + 255) / 256, 256>>>(bias_table, rel_idx);

    gemm_mma<<<dim3(768 / 128, MROWS / 128), 256, GEMM_SMEM>>>(xh, xl, wqh, wql, qkv_b, qkvp, 768);

    attn_tc<<<BWIN * 2, 128, ATTN_SMEM>>>();

    gemm_mma<<<dim3(256 / 128, MROWS / 128), 256, GEMM_SMEM>>>(ath, atl, wph, wpl, proj_b, out, 256);
}